// round 11
// baseline (speedup 1.0000x reference)
#include <cuda_runtime.h>
#include <cuda_fp16.h>
#include <cstdint>

// InstantNGPMLP fused on mma.sync m16n8k16 (tcgen05 unavailable under the
// harness's compute_103 virtual arch).
// R11 vs R10 (152us, tensor=51.5%, issue=42.7% -> per-tile serial chain
// starves the pipe during drain+epilogue):
//   - 2 tiles (32 rows) per warp, LAYER-STAGGERED: L_i(t0); L_i(t1);
//     epi(t0); epi(t1). t1's mmas fill t0's drain bubble.
//   - B-fragment LDS shared across both tiles (LDS per mma halved).
//   - launch_bounds(128,3): reg cap 170, peak live ~150. 24 tile-streams/SM.
//   - keep 2-term split (rel_err 2.0e-4), x prefetch, smem hi-frags.

#define THREADS 128
#define WARPS 4
#define NROWS 1048576
#define WTILES (NROWS / 32)   // 32768 warp-tiles of 32 rows
#define GRID 444              // 3 CTAs/SM * 148

__device__ __forceinline__ void mma16816(float d[4], const uint32_t* a, uint32_t b0, uint32_t b1) {
    asm volatile(
        "mma.sync.aligned.m16n8k16.row.col.f32.f16.f16.f32 "
        "{%0,%1,%2,%3}, {%4,%5,%6,%7}, {%8,%9}, {%0,%1,%2,%3};"
        : "+f"(d[0]), "+f"(d[1]), "+f"(d[2]), "+f"(d[3])
        : "r"(a[0]), "r"(a[1]), "r"(a[2]), "r"(a[3]), "r"(b0), "r"(b1));
}

__device__ __forceinline__ void pack_hl(float f0, float f1, uint32_t& hi, uint32_t& lo) {
    __half h0 = __float2half_rn(f0);
    __half h1 = __float2half_rn(f1);
    __half l0 = __float2half_rn(f0 - __half2float(h0));
    __half l1 = __float2half_rn(f1 - __half2float(h1));
    hi = (uint32_t)__half_as_ushort(h0) | ((uint32_t)__half_as_ushort(h1) << 16);
    lo = (uint32_t)__half_as_ushort(l0) | ((uint32_t)__half_as_ushort(l1) << 16);
}
__device__ __forceinline__ uint32_t pack_h(float f0, float f1) {
    __half h0 = __float2half_rn(f0);
    __half h1 = __float2half_rn(f1);
    return (uint32_t)__half_as_ushort(h0) | ((uint32_t)__half_as_ushort(h1) << 16);
}

// ---- smem: hi-only B fragments (~22KB) + biases ----
__shared__ uint2 sf1[512];    // L1: 2ks x 8nf x 32 lanes
__shared__ uint2 sf2[1024];   // L2: 4ks x 8nf x 32
__shared__ uint2 sf3[1024];   // L3
__shared__ uint2 sf4[256];    // L4: 4ks x 2nf x 32
__shared__ float sb1[64], sb2[64], sb3[64], sb4[16];

__device__ void stage(const float* __restrict__ W, int K, int N,
                      uint2* __restrict__ frag, int tid) {
    const int NF = N / 8, total = (K / 16) * NF * 32;
    for (int idx = tid; idx < total; idx += THREADS) {
        int lane = idx & 31, f = idx >> 5;
        int j = f % NF, ks = f / NF;
        int g = lane >> 2, t = lane & 3;
        int n = j * 8 + g;
        int k0 = ks * 16 + 2 * t;
        frag[idx] = make_uint2(pack_h(W[k0 * N + n],       W[(k0 + 1) * N + n]),
                               pack_h(W[(k0 + 8) * N + n], W[(k0 + 9) * N + n]));
    }
}

// Two-tile layer: per k-step, one shared B-frag load set feeds 32 mma
// (2 terms x 2 tiles x NF chains). Dependent mma pairs spaced 2*NF apart.
template <int KS, int NF>
__device__ __forceinline__ void layer_mma2(float (&d0)[NF][4], float (&d1)[NF][4],
                                           const uint2* __restrict__ frag,
                                           const uint32_t* __restrict__ A0h,
                                           const uint32_t* __restrict__ A0l,
                                           const uint32_t* __restrict__ A1h,
                                           const uint32_t* __restrict__ A1l,
                                           int lane) {
#pragma unroll
    for (int ks = 0; ks < KS; ks++) {
        uint2 b[NF];
#pragma unroll
        for (int j = 0; j < NF; j++) b[j] = frag[(ks * NF + j) * 32 + lane];
#pragma unroll
        for (int j = 0; j < NF; j++) mma16816(d0[j], &A0h[ks * 4], b[j].x, b[j].y);
#pragma unroll
        for (int j = 0; j < NF; j++) mma16816(d1[j], &A1h[ks * 4], b[j].x, b[j].y);
#pragma unroll
        for (int j = 0; j < NF; j++) mma16816(d0[j], &A0l[ks * 4], b[j].x, b[j].y);
#pragma unroll
        for (int j = 0; j < NF; j++) mma16816(d1[j], &A1l[ks * 4], b[j].x, b[j].y);
    }
}

__device__ __forceinline__ void epi_relu(const float (&d)[8][4],
                                         const float* __restrict__ bias, int lane,
                                         uint32_t* __restrict__ Ah, uint32_t* __restrict__ Al) {
    int t = lane & 3;
#pragma unroll
    for (int ks = 0; ks < 4; ks++) {
#pragma unroll
        for (int h = 0; h < 2; h++) {
            int j = 2 * ks + h;
            float2 b = *(const float2*)&bias[j * 8 + 2 * t];
            float f0 = fmaxf(d[j][0] + b.x, 0.0f);
            float f1 = fmaxf(d[j][1] + b.y, 0.0f);
            float f2 = fmaxf(d[j][2] + b.x, 0.0f);
            float f3 = fmaxf(d[j][3] + b.y, 0.0f);
            pack_hl(f0, f1, Ah[ks * 4 + h * 2 + 0], Al[ks * 4 + h * 2 + 0]);
            pack_hl(f2, f3, Ah[ks * 4 + h * 2 + 1], Al[ks * 4 + h * 2 + 1]);
        }
    }
}

// Raw x loads for one 16-row subtile (8 float2 per thread).
__device__ __forceinline__ void load_raw(const float* __restrict__ x, size_t rowbase,
                                         int g, int t, float2* __restrict__ raw) {
    const float* xr0 = x + (rowbase + g) * 32;
    const float* xr8 = x + (rowbase + g + 8) * 32;
#pragma unroll
    for (int ks = 0; ks < 2; ks++) {
        raw[ks * 4 + 0] = *(const float2*)&xr0[ks * 16 + 2 * t];
        raw[ks * 4 + 1] = *(const float2*)&xr8[ks * 16 + 2 * t];
        raw[ks * 4 + 2] = *(const float2*)&xr0[ks * 16 + 8 + 2 * t];
        raw[ks * 4 + 3] = *(const float2*)&xr8[ks * 16 + 8 + 2 * t];
    }
}

__global__ void __launch_bounds__(THREADS, 3)
mlp_hmma_kernel(const float* __restrict__ x,
                const float* __restrict__ Wi, const float* __restrict__ bi,
                const float* __restrict__ W1, const float* __restrict__ b1,
                const float* __restrict__ W2, const float* __restrict__ b2,
                const float* __restrict__ Wo, const float* __restrict__ bo,
                float* __restrict__ out) {
    const int tid = threadIdx.x;
    const int wid = tid >> 5;
    const int lane = tid & 31;
    const int g = lane >> 2, t = lane & 3;

    stage(Wi, 32, 64, sf1, tid);
    stage(W1, 64, 64, sf2, tid);
    stage(W2, 64, 64, sf3, tid);
    stage(Wo, 64, 16, sf4, tid);
    for (int i = tid; i < 64; i += THREADS) { sb1[i] = bi[i]; sb2[i] = b1[i]; sb3[i] = b2[i]; }
    if (tid < 16) sb4[tid] = bo[tid];
    __syncthreads();

    const int wstride = gridDim.x * WARPS;
    int wt = blockIdx.x * WARPS + wid;

    // ---- prologue: raw x loads for first warp-tile (2 subtiles) ----
    float2 raw[16];
    if (wt < WTILES) {
        load_raw(x, (size_t)wt * 32, g, t, raw);
        load_raw(x, (size_t)wt * 32 + 16, g, t, raw + 8);
    }

    for (; wt < WTILES; wt += wstride) {
        const size_t rowbase = (size_t)wt * 32;

        // ---- build A frags for both subtiles from prefetched raw ----
        uint32_t A0h[16], A0l[16], A1h[16], A1l[16];
#pragma unroll
        for (int i = 0; i < 8; i++) pack_hl(raw[i].x, raw[i].y, A0h[i], A0l[i]);
#pragma unroll
        for (int i = 0; i < 8; i++) pack_hl(raw[8 + i].x, raw[8 + i].y, A1h[i], A1l[i]);

        // ---- prefetch next warp-tile's raw x ----
        int nwt = wt + wstride;
        if (nwt < WTILES) {
            load_raw(x, (size_t)nwt * 32, g, t, raw);
            load_raw(x, (size_t)nwt * 32 + 16, g, t, raw + 8);
        }

        float d0[8][4], d1[8][4];

        // ---- L1: 32 -> 64 ----
#pragma unroll
        for (int j = 0; j < 8; j++)
#pragma unroll
            for (int e = 0; e < 4; e++) { d0[j][e] = 0.0f; d1[j][e] = 0.0f; }
        layer_mma2<2, 8>(d0, d1, sf1, A0h, A0l, A1h, A1l, lane);
        epi_relu(d0, sb1, lane, A0h, A0l);
        epi_relu(d1, sb1, lane, A1h, A1l);

        // ---- L2: 64 -> 64 ----
#pragma unroll
        for (int j = 0; j < 8; j++)
#pragma unroll
            for (int e = 0; e < 4; e++) { d0[j][e] = 0.0f; d1[j][e] = 0.0f; }
        layer_mma2<4, 8>(d0, d1, sf2, A0h, A0l, A1h, A1l, lane);
        epi_relu(d0, sb2, lane, A0h, A0l);
        epi_relu(d1, sb2, lane, A1h, A1l);

        // ---- L3: 64 -> 64 ----
#pragma unroll
        for (int j = 0; j < 8; j++)
#pragma unroll
            for (int e = 0; e < 4; e++) { d0[j][e] = 0.0f; d1[j][e] = 0.0f; }
        layer_mma2<4, 8>(d0, d1, sf3, A0h, A0l, A1h, A1l, lane);
        epi_relu(d0, sb3, lane, A0h, A0l);
        epi_relu(d1, sb3, lane, A1h, A1l);

        // ---- L4: 64 -> 16 (no relu) ----
        float e0[2][4], e1[2][4];
#pragma unroll
        for (int j = 0; j < 2; j++)
#pragma unroll
            for (int e = 0; e < 4; e++) { e0[j][e] = 0.0f; e1[j][e] = 0.0f; }
        layer_mma2<4, 2>(e0, e1, sf4, A0h, A0l, A1h, A1l, lane);

        // ---- store both subtiles ----
#pragma unroll
        for (int mt = 0; mt < 2; mt++) {
            const float (&dd)[2][4] = mt ? e1 : e0;
            float* o0 = out + (rowbase + mt * 16 + g) * 16;
            float* o8 = out + (rowbase + mt * 16 + g + 8) * 16;
#pragma unroll
            for (int j = 0; j < 2; j++) {
                float2 b = *(const float2*)&sb4[j * 8 + 2 * t];
                *(float2*)&o0[j * 8 + 2 * t] = make_float2(dd[j][0] + b.x, dd[j][1] + b.y);
                *(float2*)&o8[j * 8 + 2 * t] = make_float2(dd[j][2] + b.x, dd[j][3] + b.y);
            }
        }
    }
}

extern "C" void kernel_launch(void* const* d_in, const int* in_sizes, int n_in,
                              void* d_out, int out_size) {
    (void)in_sizes; (void)n_in; (void)out_size;
    const float* x  = (const float*)d_in[0];
    const float* Wi = (const float*)d_in[1];
    const float* bi = (const float*)d_in[2];
    const float* W1 = (const float*)d_in[3];
    const float* b1 = (const float*)d_in[4];
    const float* W2 = (const float*)d_in[5];
    const float* b2 = (const float*)d_in[6];
    const float* Wo = (const float*)d_in[7];
    const float* bo = (const float*)d_in[8];
    float* out = (float*)d_out;

    mlp_hmma_kernel<<<GRID, THREADS>>>(x, Wi, bi, W1, b1, W2, b2, Wo, bo, out);
}

// round 12
// speedup vs baseline: 1.7326x; 1.7326x over previous
#include <cuda_runtime.h>
#include <cuda_fp16.h>
#include <cstdint>

// InstantNGPMLP fused on mma.sync m16n8k16 (tcgen05 unavailable under the
// harness's compute_103 virtual arch).
// R12 vs R10 (152us best, tensor=51.5%, issue=42.7%) / R11 (2-tile regressed):
//   - PURE fp16 operands: activation lo-term dropped too. mma/tile 176 -> 88,
//     epilogue ~2.5x smaller (bias+relu+pack only).
//   - predicted rel_err 3-5e-4 (R9 measured 2.0e-4 for weights-only rounding;
//     activation rounding adds a similar independent term). Revert to R10 if
//     this breaches 1e-3.
//   - launch_bounds(128,5), grid 740 -> 20 warps/SM (fixes R10's occ ceiling).
//   - keep: R10 structure, smem hi-frags (22KB), x raw prefetch.

#define THREADS 128
#define WARPS 4
#define NROWS 1048576
#define WTILES (NROWS / 16)   // 65536 warp-tiles of 16 rows
#define GRID 740              // 5 CTAs/SM * 148

__device__ __forceinline__ void mma16816(float d[4], const uint32_t* a, uint32_t b0, uint32_t b1) {
    asm volatile(
        "mma.sync.aligned.m16n8k16.row.col.f32.f16.f16.f32 "
        "{%0,%1,%2,%3}, {%4,%5,%6,%7}, {%8,%9}, {%0,%1,%2,%3};"
        : "+f"(d[0]), "+f"(d[1]), "+f"(d[2]), "+f"(d[3])
        : "r"(a[0]), "r"(a[1]), "r"(a[2]), "r"(a[3]), "r"(b0), "r"(b1));
}

__device__ __forceinline__ uint32_t pack_h(float f0, float f1) {
    __half2 h = __floats2half2_rn(f0, f1);
    return *reinterpret_cast<uint32_t*>(&h);
}

// ---- smem: fp16 B fragments (~22KB) + biases ----
__shared__ uint2 sf1[512];    // L1: 2ks x 8nf x 32 lanes
__shared__ uint2 sf2[1024];   // L2: 4ks x 8nf x 32
__shared__ uint2 sf3[1024];   // L3
__shared__ uint2 sf4[256];    // L4: 4ks x 2nf x 32
__shared__ float sb1[64], sb2[64], sb3[64], sb4[16];

__device__ void stage(const float* __restrict__ W, int K, int N,
                      uint2* __restrict__ frag, int tid) {
    const int NF = N / 8, total = (K / 16) * NF * 32;
    for (int idx = tid; idx < total; idx += THREADS) {
        int lane = idx & 31, f = idx >> 5;
        int j = f % NF, ks = f / NF;
        int g = lane >> 2, t = lane & 3;
        int n = j * 8 + g;
        int k0 = ks * 16 + 2 * t;
        frag[idx] = make_uint2(pack_h(W[k0 * N + n],       W[(k0 + 1) * N + n]),
                               pack_h(W[(k0 + 8) * N + n], W[(k0 + 9) * N + n]));
    }
}

// Pure-fp16 layer: per k-step load NF B-frags (LDS), sweep j once.
template <int KS, int NF>
__device__ __forceinline__ void layer_mma(float (&d)[NF][4],
                                          const uint2* __restrict__ frag,
                                          const uint32_t* __restrict__ Ah, int lane) {
#pragma unroll
    for (int ks = 0; ks < KS; ks++) {
        uint2 b[NF];
#pragma unroll
        for (int j = 0; j < NF; j++) b[j] = frag[(ks * NF + j) * 32 + lane];
#pragma unroll
        for (int j = 0; j < NF; j++) mma16816(d[j], &Ah[ks * 4], b[j].x, b[j].y);
    }
}

// Epilogue: bias + relu + fp16 pack (hi only).
__device__ __forceinline__ void epi_relu(const float (&d)[8][4],
                                         const float* __restrict__ bias, int lane,
                                         uint32_t* __restrict__ Ah) {
    int t = lane & 3;
#pragma unroll
    for (int ks = 0; ks < 4; ks++) {
#pragma unroll
        for (int h = 0; h < 2; h++) {
            int j = 2 * ks + h;
            float2 b = *(const float2*)&bias[j * 8 + 2 * t];
            float f0 = fmaxf(d[j][0] + b.x, 0.0f);
            float f1 = fmaxf(d[j][1] + b.y, 0.0f);
            float f2 = fmaxf(d[j][2] + b.x, 0.0f);
            float f3 = fmaxf(d[j][3] + b.y, 0.0f);
            Ah[ks * 4 + h * 2 + 0] = pack_h(f0, f1);
            Ah[ks * 4 + h * 2 + 1] = pack_h(f2, f3);
        }
    }
}

// Raw x loads for one 16-row tile (8 float2 per thread).
__device__ __forceinline__ void load_raw(const float* __restrict__ x, size_t rowbase,
                                         int g, int t, float2 (&raw)[8]) {
    const float* xr0 = x + (rowbase + g) * 32;
    const float* xr8 = x + (rowbase + g + 8) * 32;
#pragma unroll
    for (int ks = 0; ks < 2; ks++) {
        raw[ks * 4 + 0] = *(const float2*)&xr0[ks * 16 + 2 * t];
        raw[ks * 4 + 1] = *(const float2*)&xr8[ks * 16 + 2 * t];
        raw[ks * 4 + 2] = *(const float2*)&xr0[ks * 16 + 8 + 2 * t];
        raw[ks * 4 + 3] = *(const float2*)&xr8[ks * 16 + 8 + 2 * t];
    }
}

__global__ void __launch_bounds__(THREADS, 5)
mlp_hmma_kernel(const float* __restrict__ x,
                const float* __restrict__ Wi, const float* __restrict__ bi,
                const float* __restrict__ W1, const float* __restrict__ b1,
                const float* __restrict__ W2, const float* __restrict__ b2,
                const float* __restrict__ Wo, const float* __restrict__ bo,
                float* __restrict__ out) {
    const int tid = threadIdx.x;
    const int wid = tid >> 5;
    const int lane = tid & 31;
    const int g = lane >> 2, t = lane & 3;

    stage(Wi, 32, 64, sf1, tid);
    stage(W1, 64, 64, sf2, tid);
    stage(W2, 64, 64, sf3, tid);
    stage(Wo, 64, 16, sf4, tid);
    for (int i = tid; i < 64; i += THREADS) { sb1[i] = bi[i]; sb2[i] = b1[i]; sb3[i] = b2[i]; }
    if (tid < 16) sb4[tid] = bo[tid];
    __syncthreads();

    const int wstride = gridDim.x * WARPS;
    int wt = blockIdx.x * WARPS + wid;

    // ---- prologue: raw x loads for first tile ----
    float2 raw[8];
    if (wt < WTILES) load_raw(x, (size_t)wt * 16, g, t, raw);

    for (; wt < WTILES; wt += wstride) {
        const size_t rowbase = (size_t)wt * 16;

        // ---- build fp16 A frags from prefetched raw ----
        uint32_t Ah[16];
#pragma unroll
        for (int i = 0; i < 8; i++) Ah[i] = pack_h(raw[i].x, raw[i].y);

        // ---- prefetch next tile's raw x (overlaps all mma below) ----
        int nwt = wt + wstride;
        if (nwt < WTILES) load_raw(x, (size_t)nwt * 16, g, t, raw);

        float d[8][4];

        // ---- L1: 32 -> 64 ----
#pragma unroll
        for (int j = 0; j < 8; j++)
#pragma unroll
            for (int e = 0; e < 4; e++) d[j][e] = 0.0f;
        layer_mma<2, 8>(d, sf1, Ah, lane);
        epi_relu(d, sb1, lane, Ah);

        // ---- L2: 64 -> 64 ----
#pragma unroll
        for (int j = 0; j < 8; j++)
#pragma unroll
            for (int e = 0; e < 4; e++) d[j][e] = 0.0f;
        layer_mma<4, 8>(d, sf2, Ah, lane);
        epi_relu(d, sb2, lane, Ah);

        // ---- L3: 64 -> 64 ----
#pragma unroll
        for (int j = 0; j < 8; j++)
#pragma unroll
            for (int e = 0; e < 4; e++) d[j][e] = 0.0f;
        layer_mma<4, 8>(d, sf3, Ah, lane);
        epi_relu(d, sb3, lane, Ah);

        // ---- L4: 64 -> 16 (no relu) ----
        float d4[2][4];
#pragma unroll
        for (int j = 0; j < 2; j++)
#pragma unroll
            for (int e = 0; e < 4; e++) d4[j][e] = 0.0f;
        layer_mma<4, 2>(d4, sf4, Ah, lane);

        // ---- store: rows g, g+8; cols 8j+2t, +1 ----
        {
            float* o0 = out + (rowbase + g) * 16;
            float* o8 = out + (rowbase + g + 8) * 16;
#pragma unroll
            for (int j = 0; j < 2; j++) {
                float2 b = *(const float2*)&sb4[j * 8 + 2 * t];
                *(float2*)&o0[j * 8 + 2 * t] = make_float2(d4[j][0] + b.x, d4[j][1] + b.y);
                *(float2*)&o8[j * 8 + 2 * t] = make_float2(d4[j][2] + b.x, d4[j][3] + b.y);
            }
        }
    }
}

extern "C" void kernel_launch(void* const* d_in, const int* in_sizes, int n_in,
                              void* d_out, int out_size) {
    (void)in_sizes; (void)n_in; (void)out_size;
    const float* x  = (const float*)d_in[0];
    const float* Wi = (const float*)d_in[1];
    const float* bi = (const float*)d_in[2];
    const float* W1 = (const float*)d_in[3];
    const float* b1 = (const float*)d_in[4];
    const float* W2 = (const float*)d_in[5];
    const float* b2 = (const float*)d_in[6];
    const float* Wo = (const float*)d_in[7];
    const float* bo = (const float*)d_in[8];
    float* out = (float*)d_out;

    mlp_hmma_kernel<<<GRID, THREADS>>>(x, Wi, bi, W1, b1, W2, b2, Wo, bo, out);
}

// round 13
// speedup vs baseline: 2.0600x; 1.1889x over previous
#include <cuda_runtime.h>
#include <cuda_fp16.h>
#include <cstdint>

// InstantNGPMLP fused on mma.sync m16n8k16 (tcgen05 unavailable under the
// harness's compute_103 virtual arch).
// R13 vs R12 (92.6us, L1=79.7% <- smem-byte bound, tensor=42.2%):
//   - M=32 rows/warp, B-fragment LDS shared across both 16-row subtiles:
//     smem bytes per mma HALVED (the R6/R11 idea, correct now that the
//     regime is L1-throughput-bound rather than latency-bound).
//   - pure fp16 operands (rel_err 2.98e-4 measured, 3.3x margin).
//   - launch_bounds(128,3): peak live ~155 regs < 170 cap, 12 warps/SM.
//   - keep: smem fp16 B-frags (22KB), raw x prefetch across tiles.

#define THREADS 128
#define WARPS 4
#define NROWS 1048576
#define WTILES (NROWS / 32)   // 32768 warp-tiles of 32 rows
#define GRID 444              // 3 CTAs/SM * 148

__device__ __forceinline__ void mma16816(float d[4], const uint32_t* a, uint32_t b0, uint32_t b1) {
    asm volatile(
        "mma.sync.aligned.m16n8k16.row.col.f32.f16.f16.f32 "
        "{%0,%1,%2,%3}, {%4,%5,%6,%7}, {%8,%9}, {%0,%1,%2,%3};"
        : "+f"(d[0]), "+f"(d[1]), "+f"(d[2]), "+f"(d[3])
        : "r"(a[0]), "r"(a[1]), "r"(a[2]), "r"(a[3]), "r"(b0), "r"(b1));
}

__device__ __forceinline__ uint32_t pack_h(float f0, float f1) {
    __half2 h = __floats2half2_rn(f0, f1);
    return *reinterpret_cast<uint32_t*>(&h);
}

// ---- smem: fp16 B fragments (~22KB) + biases ----
__shared__ uint2 sf1[512];    // L1: 2ks x 8nf x 32 lanes
__shared__ uint2 sf2[1024];   // L2: 4ks x 8nf x 32
__shared__ uint2 sf3[1024];   // L3
__shared__ uint2 sf4[256];    // L4: 4ks x 2nf x 32
__shared__ float sb1[64], sb2[64], sb3[64], sb4[16];

__device__ void stage(const float* __restrict__ W, int K, int N,
                      uint2* __restrict__ frag, int tid) {
    const int NF = N / 8, total = (K / 16) * NF * 32;
    for (int idx = tid; idx < total; idx += THREADS) {
        int lane = idx & 31, f = idx >> 5;
        int j = f % NF, ks = f / NF;
        int g = lane >> 2, t = lane & 3;
        int n = j * 8 + g;
        int k0 = ks * 16 + 2 * t;
        frag[idx] = make_uint2(pack_h(W[k0 * N + n],       W[(k0 + 1) * N + n]),
                               pack_h(W[(k0 + 8) * N + n], W[(k0 + 9) * N + n]));
    }
}

// Two-subtile layer, shared B loads: per k-step one LDS set feeds 2*NF mma.
template <int KS, int NF>
__device__ __forceinline__ void layer_mma2(float (&d0)[NF][4], float (&d1)[NF][4],
                                           const uint2* __restrict__ frag,
                                           const uint32_t* __restrict__ A0,
                                           const uint32_t* __restrict__ A1,
                                           int lane) {
#pragma unroll
    for (int ks = 0; ks < KS; ks++) {
        uint2 b[NF];
#pragma unroll
        for (int j = 0; j < NF; j++) b[j] = frag[(ks * NF + j) * 32 + lane];
#pragma unroll
        for (int j = 0; j < NF; j++) mma16816(d0[j], &A0[ks * 4], b[j].x, b[j].y);
#pragma unroll
        for (int j = 0; j < NF; j++) mma16816(d1[j], &A1[ks * 4], b[j].x, b[j].y);
    }
}

// Epilogue: bias + relu + fp16 pack.
__device__ __forceinline__ void epi_relu(const float (&d)[8][4],
                                         const float* __restrict__ bias, int lane,
                                         uint32_t* __restrict__ Ah) {
    int t = lane & 3;
#pragma unroll
    for (int ks = 0; ks < 4; ks++) {
#pragma unroll
        for (int h = 0; h < 2; h++) {
            int j = 2 * ks + h;
            float2 b = *(const float2*)&bias[j * 8 + 2 * t];
            float f0 = fmaxf(d[j][0] + b.x, 0.0f);
            float f1 = fmaxf(d[j][1] + b.y, 0.0f);
            float f2 = fmaxf(d[j][2] + b.x, 0.0f);
            float f3 = fmaxf(d[j][3] + b.y, 0.0f);
            Ah[ks * 4 + h * 2 + 0] = pack_h(f0, f1);
            Ah[ks * 4 + h * 2 + 1] = pack_h(f2, f3);
        }
    }
}

// Raw x loads for one 16-row subtile (8 float2 per thread).
__device__ __forceinline__ void load_raw(const float* __restrict__ x, size_t rowbase,
                                         int g, int t, float2* __restrict__ raw) {
    const float* xr0 = x + (rowbase + g) * 32;
    const float* xr8 = x + (rowbase + g + 8) * 32;
#pragma unroll
    for (int ks = 0; ks < 2; ks++) {
        raw[ks * 4 + 0] = *(const float2*)&xr0[ks * 16 + 2 * t];
        raw[ks * 4 + 1] = *(const float2*)&xr8[ks * 16 + 2 * t];
        raw[ks * 4 + 2] = *(const float2*)&xr0[ks * 16 + 8 + 2 * t];
        raw[ks * 4 + 3] = *(const float2*)&xr8[ks * 16 + 8 + 2 * t];
    }
}

__global__ void __launch_bounds__(THREADS, 3)
mlp_hmma_kernel(const float* __restrict__ x,
                const float* __restrict__ Wi, const float* __restrict__ bi,
                const float* __restrict__ W1, const float* __restrict__ b1,
                const float* __restrict__ W2, const float* __restrict__ b2,
                const float* __restrict__ Wo, const float* __restrict__ bo,
                float* __restrict__ out) {
    const int tid = threadIdx.x;
    const int wid = tid >> 5;
    const int lane = tid & 31;
    const int g = lane >> 2, t = lane & 3;

    stage(Wi, 32, 64, sf1, tid);
    stage(W1, 64, 64, sf2, tid);
    stage(W2, 64, 64, sf3, tid);
    stage(Wo, 64, 16, sf4, tid);
    for (int i = tid; i < 64; i += THREADS) { sb1[i] = bi[i]; sb2[i] = b1[i]; sb3[i] = b2[i]; }
    if (tid < 16) sb4[tid] = bo[tid];
    __syncthreads();

    const int wstride = gridDim.x * WARPS;
    int wt = blockIdx.x * WARPS + wid;

    // ---- prologue: raw x for first warp-tile (both subtiles) ----
    float2 raw[16];
    if (wt < WTILES) {
        load_raw(x, (size_t)wt * 32, g, t, raw);
        load_raw(x, (size_t)wt * 32 + 16, g, t, raw + 8);
    }

    for (; wt < WTILES; wt += wstride) {
        const size_t rowbase = (size_t)wt * 32;

        // ---- build fp16 A frags for both subtiles ----
        uint32_t A0[16], A1[16];
#pragma unroll
        for (int i = 0; i < 8; i++) A0[i] = pack_h(raw[i].x, raw[i].y);
#pragma unroll
        for (int i = 0; i < 8; i++) A1[i] = pack_h(raw[8 + i].x, raw[8 + i].y);

        // ---- prefetch next warp-tile's raw x ----
        int nwt = wt + wstride;
        if (nwt < WTILES) {
            load_raw(x, (size_t)nwt * 32, g, t, raw);
            load_raw(x, (size_t)nwt * 32 + 16, g, t, raw + 8);
        }

        float d0[8][4], d1[8][4];

        // ---- L1: 32 -> 64 ----
#pragma unroll
        for (int j = 0; j < 8; j++)
#pragma unroll
            for (int e = 0; e < 4; e++) { d0[j][e] = 0.0f; d1[j][e] = 0.0f; }
        layer_mma2<2, 8>(d0, d1, sf1, A0, A1, lane);
        epi_relu(d0, sb1, lane, A0);
        epi_relu(d1, sb1, lane, A1);

        // ---- L2: 64 -> 64 ----
#pragma unroll
        for (int j = 0; j < 8; j++)
#pragma unroll
            for (int e = 0; e < 4; e++) { d0[j][e] = 0.0f; d1[j][e] = 0.0f; }
        layer_mma2<4, 8>(d0, d1, sf2, A0, A1, lane);
        epi_relu(d0, sb2, lane, A0);
        epi_relu(d1, sb2, lane, A1);

        // ---- L3: 64 -> 64 ----
#pragma unroll
        for (int j = 0; j < 8; j++)
#pragma unroll
            for (int e = 0; e < 4; e++) { d0[j][e] = 0.0f; d1[j][e] = 0.0f; }
        layer_mma2<4, 8>(d0, d1, sf3, A0, A1, lane);
        epi_relu(d0, sb3, lane, A0);
        epi_relu(d1, sb3, lane, A1);

        // ---- L4: 64 -> 16 (no relu) ----
        float e0[2][4], e1[2][4];
#pragma unroll
        for (int j = 0; j < 2; j++)
#pragma unroll
            for (int e = 0; e < 4; e++) { e0[j][e] = 0.0f; e1[j][e] = 0.0f; }
        layer_mma2<4, 2>(e0, e1, sf4, A0, A1, lane);

        // ---- store both subtiles ----
#pragma unroll
        for (int mt = 0; mt < 2; mt++) {
            const float (&dd)[2][4] = mt ? e1 : e0;
            float* o0 = out + (rowbase + mt * 16 + g) * 16;
            float* o8 = out + (rowbase + mt * 16 + g + 8) * 16;
#pragma unroll
            for (int j = 0; j < 2; j++) {
                float2 b = *(const float2*)&sb4[j * 8 + 2 * t];
                *(float2*)&o0[j * 8 + 2 * t] = make_float2(dd[j][0] + b.x, dd[j][1] + b.y);
                *(float2*)&o8[j * 8 + 2 * t] = make_float2(dd[j][2] + b.x, dd[j][3] + b.y);
            }
        }
    }
}

extern "C" void kernel_launch(void* const* d_in, const int* in_sizes, int n_in,
                              void* d_out, int out_size) {
    (void)in_sizes; (void)n_in; (void)out_size;
    const float* x  = (const float*)d_in[0];
    const float* Wi = (const float*)d_in[1];
    const float* bi = (const float*)d_in[2];
    const float* W1 = (const float*)d_in[3];
    const float* b1 = (const float*)d_in[4];
    const float* W2 = (const float*)d_in[5];
    const float* b2 = (const float*)d_in[6];
    const float* Wo = (const float*)d_in[7];
    const float* bo = (const float*)d_in[8];
    float* out = (float*)d_out;

    mlp_hmma_kernel<<<GRID, THREADS>>>(x, Wi, bi, W1, b1, W2, b2, Wo, bo, out);
}